// round 15
// baseline (speedup 1.0000x reference)
#include <cuda_runtime.h>
#include <cfloat>
#include <cstdint>

#define N_NODES 50000
#define N_EDGES 800000
#define F_IN    256
#define H_DIM   128
#define O_DIM   64

#define NB_SCAN 128
#define CHUNK   391   // ceil(N_NODES / NB_SCAN)

// ---------------- device scratch (no allocation allowed) ----------------
__device__ int   g_degi[N_NODES];
__device__ float g_dinv[N_NODES];
__device__ int   g_row_ptr[N_NODES + 1];
__device__ int   g_cursor[N_NODES];
__device__ int   g_csr_src[N_EDGES];
__device__ float g_csr_w[N_EDGES];
__device__ int   g_chunk_sum[NB_SCAN];
__device__ int   g_chunk_off[NB_SCAN + 1];
__device__ float g_bufA[(size_t)N_NODES * H_DIM];
__device__ float g_bufB[(size_t)N_NODES * H_DIM];

// ---------------- packed f32x2 helpers (FFMA2 — sm_103 via PTX) ----------
__device__ __forceinline__ unsigned long long dup2(float f) {
    unsigned long long r;
    asm("mov.b64 %0, {%1, %1};" : "=l"(r) : "f"(f));
    return r;
}
__device__ __forceinline__ void fma2(unsigned long long& d,
                                     unsigned long long a, unsigned long long b) {
    asm("fma.rn.f32x2 %0, %1, %2, %0;" : "+l"(d) : "l"(a), "l"(b));
}
__device__ __forceinline__ float lo32(unsigned long long v) {
    return __uint_as_float((unsigned)v);
}
__device__ __forceinline__ float hi32(unsigned long long v) {
    return __uint_as_float((unsigned)(v >> 32));
}

// ---------------- setup kernels ----------------
__global__ void k_init(float* d_out) {
    int i = blockIdx.x * blockDim.x + threadIdx.x;
    if (i < N_NODES) g_degi[i] = 0;
    if (i < O_DIM)   d_out[i] = -FLT_MAX;
}

__global__ void k_hist(const int* __restrict__ dst) {
    int e4 = blockIdx.x * blockDim.x + threadIdx.x;
    if (e4 * 4 + 3 < N_EDGES) {
        int4 d = ((const int4*)dst)[e4];
        atomicAdd(&g_degi[d.x], 1);
        atomicAdd(&g_degi[d.y], 1);
        atomicAdd(&g_degi[d.z], 1);
        atomicAdd(&g_degi[d.w], 1);
    } else {
        for (int e = e4 * 4; e < N_EDGES; e++) atomicAdd(&g_degi[dst[e]], 1);
    }
}

__global__ void k_chunk_sum() {
    int b = blockIdx.x, t = threadIdx.x;
    int beg = b * CHUNK, end = min(beg + CHUNK, N_NODES);
    __shared__ int red[256];
    int s = 0;
    for (int i = beg + t; i < end; i += 256) {
        int d = g_degi[i];
        s += d;
        g_dinv[i] = rsqrtf((float)(d + 1));  // +1 self loop
    }
    red[t] = s;
    __syncthreads();
    for (int off = 128; off; off >>= 1) {
        if (t < off) red[t] += red[t + off];
        __syncthreads();
    }
    if (t == 0) g_chunk_sum[b] = red[0];
}

__global__ void k_scan_chunks() {
    __shared__ int sh[NB_SCAN];
    int t = threadIdx.x;
    sh[t] = g_chunk_sum[t];
    __syncthreads();
    for (int off = 1; off < NB_SCAN; off <<= 1) {
        int v = (t >= off) ? sh[t - off] : 0;
        __syncthreads();
        sh[t] += v;
        __syncthreads();
    }
    g_chunk_off[t + 1] = sh[t];
    if (t == 0) g_chunk_off[0] = 0;
}

__global__ void k_write_rowptr() {
    int b = blockIdx.x, t = threadIdx.x;
    int beg = b * CHUNK;
    int i = beg + t;
    __shared__ int sh[512];
    int v = (t < CHUNK && i < N_NODES) ? g_degi[i] : 0;
    sh[t] = v;
    __syncthreads();
    for (int off = 1; off < 512; off <<= 1) {
        int u = (t >= off) ? sh[t - off] : 0;
        __syncthreads();
        sh[t] += u;
        __syncthreads();
    }
    if (t < CHUNK && i < N_NODES) {
        int rp = g_chunk_off[b] + sh[t] - v;
        g_row_ptr[i] = rp;
        g_cursor[i]  = rp;
    }
    if (b == NB_SCAN - 1 && t == 0) g_row_ptr[N_NODES] = g_chunk_off[NB_SCAN];
}

__global__ void k_scatter(const int* __restrict__ src, const int* __restrict__ dst) {
    int e = blockIdx.x * blockDim.x + threadIdx.x;
    if (e >= N_EDGES) return;
    int s = src[e], d = dst[e];
    int pos = atomicAdd(&g_cursor[d], 1);
    g_csr_src[pos] = s;
    g_csr_w[pos]   = g_dinv[s];
}

// ---------------- SpMM: out[i] = dinv[i]*(sum w_e*h[src_e] + dinv[i]*h[i]) + b
__global__ void k_spmm(const float* __restrict__ h, const float* __restrict__ bias,
                       float* __restrict__ out) {
    int warp = (blockIdx.x * blockDim.x + threadIdx.x) >> 5;
    if (warp >= N_NODES) return;
    int lane = threadIdx.x & 31;
    const float4* h4 = (const float4*)h;
    float di = g_dinv[warp];
    float4 sv = h4[(size_t)warp * 32 + lane];
    float ax = sv.x * di, ay = sv.y * di, az = sv.z * di, aw = sv.w * di;
    int e    = g_row_ptr[warp];
    int eEnd = g_row_ptr[warp + 1];
    for (; e + 3 < eEnd; e += 4) {
        int   s0 = g_csr_src[e],     s1 = g_csr_src[e + 1];
        int   s2 = g_csr_src[e + 2], s3 = g_csr_src[e + 3];
        float w0 = g_csr_w[e],       w1 = g_csr_w[e + 1];
        float w2 = g_csr_w[e + 2],   w3 = g_csr_w[e + 3];
        float4 v0 = __ldg(&h4[(size_t)s0 * 32 + lane]);
        float4 v1 = __ldg(&h4[(size_t)s1 * 32 + lane]);
        float4 v2 = __ldg(&h4[(size_t)s2 * 32 + lane]);
        float4 v3 = __ldg(&h4[(size_t)s3 * 32 + lane]);
        ax = fmaf(w0, v0.x, ax); ay = fmaf(w0, v0.y, ay);
        az = fmaf(w0, v0.z, az); aw = fmaf(w0, v0.w, aw);
        ax = fmaf(w1, v1.x, ax); ay = fmaf(w1, v1.y, ay);
        az = fmaf(w1, v1.z, az); aw = fmaf(w1, v1.w, aw);
        ax = fmaf(w2, v2.x, ax); ay = fmaf(w2, v2.y, ay);
        az = fmaf(w2, v2.z, az); aw = fmaf(w2, v2.w, aw);
        ax = fmaf(w3, v3.x, ax); ay = fmaf(w3, v3.y, ay);
        az = fmaf(w3, v3.z, az); aw = fmaf(w3, v3.w, aw);
    }
    for (; e < eEnd; ++e) {
        int   s = g_csr_src[e];
        float w = g_csr_w[e];
        float4 v = __ldg(&h4[(size_t)s * 32 + lane]);
        ax = fmaf(w, v.x, ax); ay = fmaf(w, v.y, ay);
        az = fmaf(w, v.z, az); aw = fmaf(w, v.w, aw);
    }
    int cb = lane * 4;
    float4 o;
    o.x = fmaf(ax, di, bias[cb + 0]);
    o.y = fmaf(ay, di, bias[cb + 1]);
    o.z = fmaf(az, di, bias[cb + 2]);
    o.w = fmaf(aw, di, bias[cb + 3]);
    ((float4*)out)[(size_t)warp * 32 + lane] = o;
}

// ------ 128x128 tile SGEMM, BK=16, double-buffered, 8x8 microtile, FFMA2 ------
// A duplicated in smem as {a,a} u64 (dup at store time); B operand pairs come
// free as float4 -> 2x f32x2. Inner loop: 6 LDS.128 + 32 FFMA2, zero ALU dups.
// NOTE: A-row stride must be EVEN (16B-aligned rows) for the ulonglong2 loads;
// 132 gives a benign 2-way STS.64 conflict between the aK halves.
__global__ __launch_bounds__(256, 2) void sgemm128(const float* __restrict__ A,
                                                   const float* __restrict__ B,
                                                   float* __restrict__ C,
                                                   int n, int K) {
    const int M = 128;
    __shared__ unsigned long long Asd[2][16][132];  // dup'd A, 16B-aligned rows
    __shared__ float Bs[2][16][132];
    const int tid = threadIdx.x;
    const int rowBase = blockIdx.x * 128;

    const int aRow = tid >> 1;          // 0..127
    const int aK   = (tid & 1) * 8;     // 0 or 8
    const int bK   = tid >> 4;          // 0..15
    const int bC   = (tid & 15) * 8;    // 0..120
    const int tx   = tid & 15;
    const int ty   = tid >> 4;

    // acc2[i][jp]: row i (of this thread's 8), col-pair jp -> cols {2jp,2jp+1}
    unsigned long long acc2[8][4];
#pragma unroll
    for (int i = 0; i < 8; i++)
#pragma unroll
        for (int j = 0; j < 4; j++) acc2[i][j] = 0ull;

    const bool aValid = (rowBase + aRow) < n;
    const float* Aptr = A + (size_t)(rowBase + aRow) * K;
    const float* Bptr = B + (size_t)bK * M + bC;

    const int NIT = K / 16;

    // prologue: load tile 0 into buffer 0
    {
        float4 a0 = aValid ? *(const float4*)(Aptr + aK)
                           : make_float4(0.f, 0.f, 0.f, 0.f);
        float4 a1 = aValid ? *(const float4*)(Aptr + aK + 4)
                           : make_float4(0.f, 0.f, 0.f, 0.f);
        Asd[0][aK + 0][aRow] = dup2(a0.x); Asd[0][aK + 1][aRow] = dup2(a0.y);
        Asd[0][aK + 2][aRow] = dup2(a0.z); Asd[0][aK + 3][aRow] = dup2(a0.w);
        Asd[0][aK + 4][aRow] = dup2(a1.x); Asd[0][aK + 5][aRow] = dup2(a1.y);
        Asd[0][aK + 6][aRow] = dup2(a1.z); Asd[0][aK + 7][aRow] = dup2(a1.w);
        *(float4*)&Bs[0][bK][bC]     = *(const float4*)(Bptr);
        *(float4*)&Bs[0][bK][bC + 4] = *(const float4*)(Bptr + 4);
    }
    __syncthreads();

    for (int it = 0; it < NIT; it++) {
        const int cur = it & 1, nxt = cur ^ 1;
        float4 pa0, pa1, pb0, pb1;
        const bool hasNext = (it + 1) < NIT;
        if (hasNext) {
            int k0 = (it + 1) * 16;
            pa0 = aValid ? *(const float4*)(Aptr + k0 + aK)
                         : make_float4(0.f, 0.f, 0.f, 0.f);
            pa1 = aValid ? *(const float4*)(Aptr + k0 + aK + 4)
                         : make_float4(0.f, 0.f, 0.f, 0.f);
            pb0 = *(const float4*)(Bptr + (size_t)k0 * M);
            pb1 = *(const float4*)(Bptr + (size_t)k0 * M + 4);
        }
#pragma unroll
        for (int k = 0; k < 16; k++) {
            ulonglong2 a01 = *(const ulonglong2*)&Asd[cur][k][ty * 4];
            ulonglong2 a23 = *(const ulonglong2*)&Asd[cur][k][ty * 4 + 2];
            ulonglong2 a45 = *(const ulonglong2*)&Asd[cur][k][64 + ty * 4];
            ulonglong2 a67 = *(const ulonglong2*)&Asd[cur][k][64 + ty * 4 + 2];
            float4 b0f = *(const float4*)&Bs[cur][k][tx * 4];
            float4 b1f = *(const float4*)&Bs[cur][k][64 + tx * 4];
            ulonglong2 bp0 = *(const ulonglong2*)&b0f;   // {b0,b1},{b2,b3}
            ulonglong2 bp1 = *(const ulonglong2*)&b1f;
            unsigned long long a[8]  = {a01.x, a01.y, a23.x, a23.y,
                                        a45.x, a45.y, a67.x, a67.y};
            unsigned long long bp[4] = {bp0.x, bp0.y, bp1.x, bp1.y};
#pragma unroll
            for (int i = 0; i < 8; i++)
#pragma unroll
                for (int j = 0; j < 4; j++)
                    fma2(acc2[i][j], a[i], bp[j]);
        }
        if (hasNext) {
            Asd[nxt][aK + 0][aRow] = dup2(pa0.x); Asd[nxt][aK + 1][aRow] = dup2(pa0.y);
            Asd[nxt][aK + 2][aRow] = dup2(pa0.z); Asd[nxt][aK + 3][aRow] = dup2(pa0.w);
            Asd[nxt][aK + 4][aRow] = dup2(pa1.x); Asd[nxt][aK + 5][aRow] = dup2(pa1.y);
            Asd[nxt][aK + 6][aRow] = dup2(pa1.z); Asd[nxt][aK + 7][aRow] = dup2(pa1.w);
            *(float4*)&Bs[nxt][bK][bC]     = pb0;
            *(float4*)&Bs[nxt][bK][bC + 4] = pb1;
        }
        __syncthreads();
    }

#pragma unroll
    for (int i = 0; i < 8; i++) {
        int rOff = (i < 4) ? (ty * 4 + i) : (64 + ty * 4 + (i - 4));
        int r = rowBase + rOff;
        if (r < n) {
            *(float4*)(C + (size_t)r * M + tx * 4) =
                make_float4(lo32(acc2[i][0]), hi32(acc2[i][0]),
                            lo32(acc2[i][1]), hi32(acc2[i][1]));
            *(float4*)(C + (size_t)r * M + 64 + tx * 4) =
                make_float4(lo32(acc2[i][2]), hi32(acc2[i][2]),
                            lo32(acc2[i][3]), hi32(acc2[i][3]));
        }
    }
}

// ---------------- fused final GEMM (K=128 -> O=64) + global max pool ------
__device__ __forceinline__ void atomicMaxFloat(float* addr, float val) {
    if (val >= 0.f) atomicMax((int*)addr, __float_as_int(val));
    else            atomicMin((unsigned int*)addr, __float_as_uint(val));
}

__global__ __launch_bounds__(256) void k_gemm_maxpool(const float* __restrict__ A,
                                                      const float* __restrict__ B,
                                                      const float* __restrict__ bias,
                                                      float* __restrict__ d_out,
                                                      int n) {
    const int K = H_DIM, M = O_DIM, BM = 64, BK = 16;
    __shared__ float As[BK][BM];
    __shared__ float Bs[BK][M];
    __shared__ float shmax[16][M];
    const int tid = threadIdx.x;
    const int ty  = tid / 16;
    const int tx  = tid % 16;
    const int rowBase = blockIdx.x * BM;

    float acc[4][4];
#pragma unroll
    for (int i = 0; i < 4; i++)
#pragma unroll
        for (int j = 0; j < 4; j++) acc[i][j] = 0.f;

    const int aRow = tid >> 2;
    const int aKq  = (tid & 3) * 4;
    const int bK   = tid >> 4;
    const int bCq  = (tid & 15) * 4;

    for (int k0 = 0; k0 < K; k0 += BK) {
        float4 av = make_float4(0.f, 0.f, 0.f, 0.f);
        int gr = rowBase + aRow;
        if (gr < n) av = *(const float4*)(A + (size_t)gr * K + k0 + aKq);
        As[aKq + 0][aRow] = av.x;
        As[aKq + 1][aRow] = av.y;
        As[aKq + 2][aRow] = av.z;
        As[aKq + 3][aRow] = av.w;
        *(float4*)&Bs[bK][bCq] = *(const float4*)(B + (size_t)(k0 + bK) * M + bCq);
        __syncthreads();
#pragma unroll
        for (int k = 0; k < BK; k++) {
            float4 ra4 = *(const float4*)&As[k][ty * 4];
            float4 rb4 = *(const float4*)&Bs[k][tx * 4];
            float ra[4] = {ra4.x, ra4.y, ra4.z, ra4.w};
            float rb[4] = {rb4.x, rb4.y, rb4.z, rb4.w};
#pragma unroll
            for (int i = 0; i < 4; i++)
#pragma unroll
                for (int j = 0; j < 4; j++)
                    acc[i][j] = fmaf(ra[i], rb[j], acc[i][j]);
        }
        __syncthreads();
    }
#pragma unroll
    for (int j = 0; j < 4; j++) {
        int gc = tx * 4 + j;
        float bj = bias[gc];
        float m = -FLT_MAX;
#pragma unroll
        for (int i = 0; i < 4; i++) {
            int gr = rowBase + ty * 4 + i;
            if (gr < n) m = fmaxf(m, acc[i][j] + bj);
        }
        shmax[ty][gc] = m;
    }
    __syncthreads();
    if (tid < M) {
        float m = -FLT_MAX;
#pragma unroll
        for (int t = 0; t < 16; t++) m = fmaxf(m, shmax[t][tid]);
        atomicMaxFloat(&d_out[tid], m);
    }
}

// ---------------- launch ----------------
extern "C" void kernel_launch(void* const* d_in, const int* in_sizes, int n_in,
                              void* d_out, int out_size) {
    const float* x  = (const float*)d_in[0];
    const int*   ei = (const int*)d_in[1];
    const float* W0 = (const float*)d_in[3];
    const float* b0 = (const float*)d_in[4];
    const float* W1 = (const float*)d_in[5];
    const float* b1 = (const float*)d_in[6];
    const float* W2 = (const float*)d_in[7];
    const float* b2 = (const float*)d_in[8];
    const float* Wl = (const float*)d_in[9];
    const float* bl = (const float*)d_in[10];
    float* out = (float*)d_out;

    const int* src = ei;             // edge_index[0]
    const int* dst = ei + N_EDGES;   // edge_index[1]

    float *bufA, *bufB;
    cudaGetSymbolAddress((void**)&bufA, g_bufA);
    cudaGetSymbolAddress((void**)&bufB, g_bufB);

    const int TB = 256;
    int gemmBlocks = (N_NODES + 127) / 128;               // 391
    int spmmBlocks = (N_NODES * 32 + TB - 1) / TB;        // warp per row

    // fork: prep chain on side stream, GEMM0 on main (capture) stream
    cudaStream_t s2;
    cudaStreamCreateWithFlags(&s2, cudaStreamNonBlocking);
    cudaEvent_t evF, evJ;
    cudaEventCreateWithFlags(&evF, cudaEventDisableTiming);
    cudaEventCreateWithFlags(&evJ, cudaEventDisableTiming);

    cudaEventRecord(evF, 0);
    cudaStreamWaitEvent(s2, evF, 0);

    k_init<<<(N_NODES + TB - 1) / TB, TB, 0, s2>>>(out);
    k_hist<<<((N_EDGES / 4) + TB - 1) / TB, TB, 0, s2>>>(dst);
    k_chunk_sum<<<NB_SCAN, 256, 0, s2>>>();
    k_scan_chunks<<<1, NB_SCAN, 0, s2>>>();
    k_write_rowptr<<<NB_SCAN, 512, 0, s2>>>();
    k_scatter<<<(N_EDGES + TB - 1) / TB, TB, 0, s2>>>(src, dst);
    cudaEventRecord(evJ, s2);

    // overlaps with the prep chain above
    sgemm128<<<gemmBlocks, 256>>>(x, W0, bufA, N_NODES, F_IN);

    // join: SpMM needs CSR + dinv + GEMM0 output
    cudaStreamWaitEvent(0, evJ, 0);

    k_spmm<<<spmmBlocks, TB>>>(bufA, b0, bufB);

    sgemm128<<<gemmBlocks, 256>>>(bufB, W1, bufA, N_NODES, H_DIM);
    k_spmm<<<spmmBlocks, TB>>>(bufA, b1, bufB);

    sgemm128<<<gemmBlocks, 256>>>(bufB, W2, bufA, N_NODES, H_DIM);
    k_spmm<<<spmmBlocks, TB>>>(bufA, b2, bufB);

    k_gemm_maxpool<<<(N_NODES + 63) / 64, 256>>>(bufB, Wl, bl, out, N_NODES);
}

// round 16
// speedup vs baseline: 1.0836x; 1.0836x over previous
#include <cuda_runtime.h>
#include <cfloat>
#include <cstdint>

#define N_NODES 50000
#define N_EDGES 800000
#define F_IN    256
#define H_DIM   128
#define O_DIM   64

#define NB_SCAN 128
#define CHUNK   391   // ceil(N_NODES / NB_SCAN)
#define HALF_ROWS 25088   // 196 tiles of 128; remainder 195 tiles

// ---------------- device scratch (no allocation allowed) ----------------
__device__ int   g_degi[N_NODES];
__device__ float g_dinv[N_NODES];
__device__ int   g_row_ptr[N_NODES + 1];
__device__ int   g_cursor[N_NODES];
__device__ int   g_csr_src[N_EDGES];
__device__ float g_csr_w[N_EDGES];
__device__ int   g_chunk_sum[NB_SCAN];
__device__ int   g_chunk_off[NB_SCAN + 1];
__device__ float g_bufA[(size_t)N_NODES * H_DIM];
__device__ float g_bufB[(size_t)N_NODES * H_DIM];
__device__ float g_bufC[(size_t)N_NODES * H_DIM];

// ---------------- packed f32x2 helpers (FFMA2 — sm_103 via PTX) ----------
__device__ __forceinline__ unsigned long long dup2(float f) {
    unsigned long long r;
    asm("mov.b64 %0, {%1, %1};" : "=l"(r) : "f"(f));
    return r;
}
__device__ __forceinline__ void fma2(unsigned long long& d,
                                     unsigned long long a, unsigned long long b) {
    asm("fma.rn.f32x2 %0, %1, %2, %0;" : "+l"(d) : "l"(a), "l"(b));
}
__device__ __forceinline__ float lo32(unsigned long long v) {
    return __uint_as_float((unsigned)v);
}
__device__ __forceinline__ float hi32(unsigned long long v) {
    return __uint_as_float((unsigned)(v >> 32));
}

// ---------------- setup kernels ----------------
__global__ void k_init(float* d_out) {
    int i = blockIdx.x * blockDim.x + threadIdx.x;
    if (i < N_NODES) g_degi[i] = 0;
    if (i < O_DIM)   d_out[i] = -FLT_MAX;
}

__global__ void k_hist(const int* __restrict__ dst) {
    int e4 = blockIdx.x * blockDim.x + threadIdx.x;
    if (e4 * 4 + 3 < N_EDGES) {
        int4 d = ((const int4*)dst)[e4];
        atomicAdd(&g_degi[d.x], 1);
        atomicAdd(&g_degi[d.y], 1);
        atomicAdd(&g_degi[d.z], 1);
        atomicAdd(&g_degi[d.w], 1);
    } else {
        for (int e = e4 * 4; e < N_EDGES; e++) atomicAdd(&g_degi[dst[e]], 1);
    }
}

__global__ void k_chunk_sum() {
    int b = blockIdx.x, t = threadIdx.x;
    int beg = b * CHUNK, end = min(beg + CHUNK, N_NODES);
    __shared__ int red[256];
    int s = 0;
    for (int i = beg + t; i < end; i += 256) {
        int d = g_degi[i];
        s += d;
        g_dinv[i] = rsqrtf((float)(d + 1));  // +1 self loop
    }
    red[t] = s;
    __syncthreads();
    for (int off = 128; off; off >>= 1) {
        if (t < off) red[t] += red[t + off];
        __syncthreads();
    }
    if (t == 0) g_chunk_sum[b] = red[0];
}

__global__ void k_scan_chunks() {
    __shared__ int sh[NB_SCAN];
    int t = threadIdx.x;
    sh[t] = g_chunk_sum[t];
    __syncthreads();
    for (int off = 1; off < NB_SCAN; off <<= 1) {
        int v = (t >= off) ? sh[t - off] : 0;
        __syncthreads();
        sh[t] += v;
        __syncthreads();
    }
    g_chunk_off[t + 1] = sh[t];
    if (t == 0) g_chunk_off[0] = 0;
}

__global__ void k_write_rowptr() {
    int b = blockIdx.x, t = threadIdx.x;
    int beg = b * CHUNK;
    int i = beg + t;
    __shared__ int sh[512];
    int v = (t < CHUNK && i < N_NODES) ? g_degi[i] : 0;
    sh[t] = v;
    __syncthreads();
    for (int off = 1; off < 512; off <<= 1) {
        int u = (t >= off) ? sh[t - off] : 0;
        __syncthreads();
        sh[t] += u;
        __syncthreads();
    }
    if (t < CHUNK && i < N_NODES) {
        int rp = g_chunk_off[b] + sh[t] - v;
        g_row_ptr[i] = rp;
        g_cursor[i]  = rp;
    }
    if (b == NB_SCAN - 1 && t == 0) g_row_ptr[N_NODES] = g_chunk_off[NB_SCAN];
}

__global__ void k_scatter(const int* __restrict__ src, const int* __restrict__ dst) {
    int e = blockIdx.x * blockDim.x + threadIdx.x;
    if (e >= N_EDGES) return;
    int s = src[e], d = dst[e];
    int pos = atomicAdd(&g_cursor[d], 1);
    g_csr_src[pos] = s;
    g_csr_w[pos]   = g_dinv[s];
}

// ---- SpMM rows [rowOff,rowEnd): out[i] = dinv[i]*(sum w*h[src] + dinv[i]*h[i]) + b
__global__ void k_spmm(const float* __restrict__ h, const float* __restrict__ bias,
                       float* __restrict__ out, int rowOff, int rowEnd) {
    int warp = rowOff + ((blockIdx.x * blockDim.x + threadIdx.x) >> 5);
    if (warp >= rowEnd) return;
    int lane = threadIdx.x & 31;
    const float4* h4 = (const float4*)h;
    float di = g_dinv[warp];
    float4 sv = h4[(size_t)warp * 32 + lane];
    float ax = sv.x * di, ay = sv.y * di, az = sv.z * di, aw = sv.w * di;
    int e    = g_row_ptr[warp];
    int eEnd = g_row_ptr[warp + 1];
    for (; e + 3 < eEnd; e += 4) {
        int   s0 = g_csr_src[e],     s1 = g_csr_src[e + 1];
        int   s2 = g_csr_src[e + 2], s3 = g_csr_src[e + 3];
        float w0 = g_csr_w[e],       w1 = g_csr_w[e + 1];
        float w2 = g_csr_w[e + 2],   w3 = g_csr_w[e + 3];
        float4 v0 = __ldg(&h4[(size_t)s0 * 32 + lane]);
        float4 v1 = __ldg(&h4[(size_t)s1 * 32 + lane]);
        float4 v2 = __ldg(&h4[(size_t)s2 * 32 + lane]);
        float4 v3 = __ldg(&h4[(size_t)s3 * 32 + lane]);
        ax = fmaf(w0, v0.x, ax); ay = fmaf(w0, v0.y, ay);
        az = fmaf(w0, v0.z, az); aw = fmaf(w0, v0.w, aw);
        ax = fmaf(w1, v1.x, ax); ay = fmaf(w1, v1.y, ay);
        az = fmaf(w1, v1.z, az); aw = fmaf(w1, v1.w, aw);
        ax = fmaf(w2, v2.x, ax); ay = fmaf(w2, v2.y, ay);
        az = fmaf(w2, v2.z, az); aw = fmaf(w2, v2.w, aw);
        ax = fmaf(w3, v3.x, ax); ay = fmaf(w3, v3.y, ay);
        az = fmaf(w3, v3.z, az); aw = fmaf(w3, v3.w, aw);
    }
    for (; e < eEnd; ++e) {
        int   s = g_csr_src[e];
        float w = g_csr_w[e];
        float4 v = __ldg(&h4[(size_t)s * 32 + lane]);
        ax = fmaf(w, v.x, ax); ay = fmaf(w, v.y, ay);
        az = fmaf(w, v.z, az); aw = fmaf(w, v.w, aw);
    }
    int cb = lane * 4;
    float4 o;
    o.x = fmaf(ax, di, bias[cb + 0]);
    o.y = fmaf(ay, di, bias[cb + 1]);
    o.z = fmaf(az, di, bias[cb + 2]);
    o.w = fmaf(aw, di, bias[cb + 3]);
    ((float4*)out)[(size_t)warp * 32 + lane] = o;
}

// ------ 128x128 tile SGEMM, BK=16, double-buffered, 8x8 microtile, FFMA2 ------
// (R12 form: dup2 of B scalars in-loop; movs hide under the 50% fma-issue cap)
__global__ __launch_bounds__(256, 2) void sgemm128(const float* __restrict__ A,
                                                   const float* __restrict__ B,
                                                   float* __restrict__ C,
                                                   int n, int K, int rowOff) {
    const int M = 128;
    __shared__ float As[2][16][132];
    __shared__ float Bs[2][16][132];
    const int tid = threadIdx.x;
    const int rowBase = rowOff + blockIdx.x * 128;

    const int aRow = tid >> 1;          // 0..127
    const int aK   = (tid & 1) * 8;     // 0 or 8
    const int bK   = tid >> 4;          // 0..15
    const int bC   = (tid & 15) * 8;    // 0..120
    const int tx   = tid & 15;
    const int ty   = tid >> 4;

    unsigned long long acc2[4][8];
#pragma unroll
    for (int p = 0; p < 4; p++)
#pragma unroll
        for (int j = 0; j < 8; j++) acc2[p][j] = 0ull;

    const bool aValid = (rowBase + aRow) < n;
    const float* Aptr = A + (size_t)(rowBase + aRow) * K;
    const float* Bptr = B + (size_t)bK * M + bC;

    const int NIT = K / 16;

    // prologue: load tile 0 into buffer 0
    {
        float4 a0 = aValid ? *(const float4*)(Aptr + aK)
                           : make_float4(0.f, 0.f, 0.f, 0.f);
        float4 a1 = aValid ? *(const float4*)(Aptr + aK + 4)
                           : make_float4(0.f, 0.f, 0.f, 0.f);
        As[0][aK + 0][aRow] = a0.x; As[0][aK + 1][aRow] = a0.y;
        As[0][aK + 2][aRow] = a0.z; As[0][aK + 3][aRow] = a0.w;
        As[0][aK + 4][aRow] = a1.x; As[0][aK + 5][aRow] = a1.y;
        As[0][aK + 6][aRow] = a1.z; As[0][aK + 7][aRow] = a1.w;
        *(float4*)&Bs[0][bK][bC]     = *(const float4*)(Bptr);
        *(float4*)&Bs[0][bK][bC + 4] = *(const float4*)(Bptr + 4);
    }
    __syncthreads();

    for (int it = 0; it < NIT; it++) {
        const int cur = it & 1, nxt = cur ^ 1;
        float4 pa0, pa1, pb0, pb1;
        const bool hasNext = (it + 1) < NIT;
        if (hasNext) {
            int k0 = (it + 1) * 16;
            pa0 = aValid ? *(const float4*)(Aptr + k0 + aK)
                         : make_float4(0.f, 0.f, 0.f, 0.f);
            pa1 = aValid ? *(const float4*)(Aptr + k0 + aK + 4)
                         : make_float4(0.f, 0.f, 0.f, 0.f);
            pb0 = *(const float4*)(Bptr + (size_t)k0 * M);
            pb1 = *(const float4*)(Bptr + (size_t)k0 * M + 4);
        }
#pragma unroll
        for (int k = 0; k < 16; k++) {
            ulonglong2 aA = *(const ulonglong2*)&As[cur][k][ty * 4];
            ulonglong2 aB = *(const ulonglong2*)&As[cur][k][64 + ty * 4];
            float4 b0 = *(const float4*)&Bs[cur][k][tx * 4];
            float4 b1 = *(const float4*)&Bs[cur][k][64 + tx * 4];
            unsigned long long ap[4] = {aA.x, aA.y, aB.x, aB.y};
            unsigned long long bd[8] = {dup2(b0.x), dup2(b0.y), dup2(b0.z), dup2(b0.w),
                                        dup2(b1.x), dup2(b1.y), dup2(b1.z), dup2(b1.w)};
#pragma unroll
            for (int p = 0; p < 4; p++)
#pragma unroll
                for (int j = 0; j < 8; j++)
                    fma2(acc2[p][j], ap[p], bd[j]);
        }
        if (hasNext) {
            As[nxt][aK + 0][aRow] = pa0.x; As[nxt][aK + 1][aRow] = pa0.y;
            As[nxt][aK + 2][aRow] = pa0.z; As[nxt][aK + 3][aRow] = pa0.w;
            As[nxt][aK + 4][aRow] = pa1.x; As[nxt][aK + 5][aRow] = pa1.y;
            As[nxt][aK + 6][aRow] = pa1.z; As[nxt][aK + 7][aRow] = pa1.w;
            *(float4*)&Bs[nxt][bK][bC]     = pb0;
            *(float4*)&Bs[nxt][bK][bC + 4] = pb1;
        }
        __syncthreads();
    }

#pragma unroll
    for (int p = 0; p < 4; p++) {
        int rOff = (p < 2) ? (ty * 4 + p * 2) : (64 + ty * 4 + (p - 2) * 2);
        int rLo = rowBase + rOff;
        int rHi = rLo + 1;
        if (rLo < n) {
            *(float4*)(C + (size_t)rLo * M + tx * 4) =
                make_float4(lo32(acc2[p][0]), lo32(acc2[p][1]), lo32(acc2[p][2]), lo32(acc2[p][3]));
            *(float4*)(C + (size_t)rLo * M + 64 + tx * 4) =
                make_float4(lo32(acc2[p][4]), lo32(acc2[p][5]), lo32(acc2[p][6]), lo32(acc2[p][7]));
        }
        if (rHi < n) {
            *(float4*)(C + (size_t)rHi * M + tx * 4) =
                make_float4(hi32(acc2[p][0]), hi32(acc2[p][1]), hi32(acc2[p][2]), hi32(acc2[p][3]));
            *(float4*)(C + (size_t)rHi * M + 64 + tx * 4) =
                make_float4(hi32(acc2[p][4]), hi32(acc2[p][5]), hi32(acc2[p][6]), hi32(acc2[p][7]));
        }
    }
}

// ---------------- fused final GEMM (K=128 -> O=64) + global max pool ------
__device__ __forceinline__ void atomicMaxFloat(float* addr, float val) {
    if (val >= 0.f) atomicMax((int*)addr, __float_as_int(val));
    else            atomicMin((unsigned int*)addr, __float_as_uint(val));
}

__global__ __launch_bounds__(256) void k_gemm_maxpool(const float* __restrict__ A,
                                                      const float* __restrict__ B,
                                                      const float* __restrict__ bias,
                                                      float* __restrict__ d_out,
                                                      int rowOff, int rowEnd) {
    const int K = H_DIM, M = O_DIM, BM = 64, BK = 16;
    __shared__ float As[BK][BM];
    __shared__ float Bs[BK][M];
    __shared__ float shmax[16][M];
    const int tid = threadIdx.x;
    const int ty  = tid / 16;
    const int tx  = tid % 16;
    const int rowBase = rowOff + blockIdx.x * BM;

    float acc[4][4];
#pragma unroll
    for (int i = 0; i < 4; i++)
#pragma unroll
        for (int j = 0; j < 4; j++) acc[i][j] = 0.f;

    const int aRow = tid >> 2;
    const int aKq  = (tid & 3) * 4;
    const int bK   = tid >> 4;
    const int bCq  = (tid & 15) * 4;

    for (int k0 = 0; k0 < K; k0 += BK) {
        float4 av = make_float4(0.f, 0.f, 0.f, 0.f);
        int gr = rowBase + aRow;
        if (gr < rowEnd) av = *(const float4*)(A + (size_t)gr * K + k0 + aKq);
        As[aKq + 0][aRow] = av.x;
        As[aKq + 1][aRow] = av.y;
        As[aKq + 2][aRow] = av.z;
        As[aKq + 3][aRow] = av.w;
        *(float4*)&Bs[bK][bCq] = *(const float4*)(B + (size_t)(k0 + bK) * M + bCq);
        __syncthreads();
#pragma unroll
        for (int k = 0; k < BK; k++) {
            float4 ra4 = *(const float4*)&As[k][ty * 4];
            float4 rb4 = *(const float4*)&Bs[k][tx * 4];
            float ra[4] = {ra4.x, ra4.y, ra4.z, ra4.w};
            float rb[4] = {rb4.x, rb4.y, rb4.z, rb4.w};
#pragma unroll
            for (int i = 0; i < 4; i++)
#pragma unroll
                for (int j = 0; j < 4; j++)
                    acc[i][j] = fmaf(ra[i], rb[j], acc[i][j]);
        }
        __syncthreads();
    }
#pragma unroll
    for (int j = 0; j < 4; j++) {
        int gc = tx * 4 + j;
        float bj = bias[gc];
        float m = -FLT_MAX;
#pragma unroll
        for (int i = 0; i < 4; i++) {
            int gr = rowBase + ty * 4 + i;
            if (gr < rowEnd) m = fmaxf(m, acc[i][j] + bj);
        }
        shmax[ty][gc] = m;
    }
    __syncthreads();
    if (tid < M) {
        float m = -FLT_MAX;
#pragma unroll
        for (int t = 0; t < 16; t++) m = fmaxf(m, shmax[t][tid]);
        atomicMaxFloat(&d_out[tid], m);
    }
}

// ---------------- launch ----------------
extern "C" void kernel_launch(void* const* d_in, const int* in_sizes, int n_in,
                              void* d_out, int out_size) {
    const float* x  = (const float*)d_in[0];
    const int*   ei = (const int*)d_in[1];
    const float* W0 = (const float*)d_in[3];
    const float* b0 = (const float*)d_in[4];
    const float* W1 = (const float*)d_in[5];
    const float* b1 = (const float*)d_in[6];
    const float* W2 = (const float*)d_in[7];
    const float* b2 = (const float*)d_in[8];
    const float* Wl = (const float*)d_in[9];
    const float* bl = (const float*)d_in[10];
    float* out = (float*)d_out;

    const int* src = ei;             // edge_index[0]
    const int* dst = ei + N_EDGES;   // edge_index[1]

    float *bufA, *bufB, *bufC;
    cudaGetSymbolAddress((void**)&bufA, g_bufA);
    cudaGetSymbolAddress((void**)&bufB, g_bufB);
    cudaGetSymbolAddress((void**)&bufC, g_bufC);

    const int TB = 256;
    // halves (tile-aligned)
    const int R0 = 0, R1 = HALF_ROWS, R2 = N_NODES;
    const int gemmFull = (N_NODES + 127) / 128;       // 391
    const int gemmH0   = (R1 - R0) / 128;             // 196
    const int gemmH1   = (R2 - R1 + 127) / 128;       // 195
    const int spmmH0   = ((R1 - R0) * 32 + TB - 1) / TB;
    const int spmmH1   = ((R2 - R1) * 32 + TB - 1) / TB;
    const int gmpH0    = (R1 - R0 + 63) / 64;
    const int gmpH1    = (R2 - R1 + 63) / 64;

    cudaStream_t s2;
    cudaStreamCreateWithFlags(&s2, cudaStreamNonBlocking);
    cudaEvent_t evF, evPrep, evG0, eA, eB, eC, eD, evEnd2;
    cudaEventCreateWithFlags(&evF,    cudaEventDisableTiming);
    cudaEventCreateWithFlags(&evPrep, cudaEventDisableTiming);
    cudaEventCreateWithFlags(&evG0,   cudaEventDisableTiming);
    cudaEventCreateWithFlags(&eA,     cudaEventDisableTiming);
    cudaEventCreateWithFlags(&eB,     cudaEventDisableTiming);
    cudaEventCreateWithFlags(&eC,     cudaEventDisableTiming);
    cudaEventCreateWithFlags(&eD,     cudaEventDisableTiming);
    cudaEventCreateWithFlags(&evEnd2, cudaEventDisableTiming);

    // fork
    cudaEventRecord(evF, 0);
    cudaStreamWaitEvent(s2, evF, 0);

    // lane s2: prep chain
    k_init<<<(N_NODES + TB - 1) / TB, TB, 0, s2>>>(out);
    k_hist<<<((N_EDGES / 4) + TB - 1) / TB, TB, 0, s2>>>(dst);
    k_chunk_sum<<<NB_SCAN, 256, 0, s2>>>();
    k_scan_chunks<<<1, NB_SCAN, 0, s2>>>();
    k_write_rowptr<<<NB_SCAN, 512, 0, s2>>>();
    k_scatter<<<(N_EDGES + TB - 1) / TB, TB, 0, s2>>>(src, dst);
    cudaEventRecord(evPrep, s2);

    // lane s0: GEMM0 full (x @ W0 -> bufA), overlaps prep
    sgemm128<<<gemmFull, 256>>>(x, W0, bufA, N_NODES, F_IN, 0);
    cudaEventRecord(evG0, 0);

    // --- layer 0 SpMM: bufA -> bufB (needs prep + GEMM0) ---
    cudaStreamWaitEvent(0, evPrep, 0);
    k_spmm<<<spmmH0, TB>>>(bufA, b0, bufB, R0, R1);
    cudaStreamWaitEvent(s2, evG0, 0);
    k_spmm<<<spmmH1, TB, 0, s2>>>(bufA, b0, bufB, R1, R2);

    // --- GEMM1: bufB -> bufC (each half needs only its own SpMM rows) ---
    sgemm128<<<gemmH0, 256>>>(bufB, W1, bufC, N_NODES, H_DIM, R0);
    cudaEventRecord(eA, 0);
    sgemm128<<<gemmH1, 256, 0, s2>>>(bufB, W1, bufC, N_NODES, H_DIM, R1);
    cudaEventRecord(eB, s2);

    // --- SpMM1: bufC -> bufA (needs BOTH GEMM1 halves) ---
    cudaStreamWaitEvent(0, eB, 0);
    k_spmm<<<spmmH0, TB>>>(bufC, b1, bufA, R0, R1);
    cudaStreamWaitEvent(s2, eA, 0);
    k_spmm<<<spmmH1, TB, 0, s2>>>(bufC, b1, bufA, R1, R2);

    // --- GEMM2: bufA -> bufB ---
    sgemm128<<<gemmH0, 256>>>(bufA, W2, bufB, N_NODES, H_DIM, R0);
    cudaEventRecord(eC, 0);
    sgemm128<<<gemmH1, 256, 0, s2>>>(bufA, W2, bufB, N_NODES, H_DIM, R1);
    cudaEventRecord(eD, s2);

    // --- SpMM2: bufB -> bufC (needs BOTH GEMM2 halves) ---
    cudaStreamWaitEvent(0, eD, 0);
    k_spmm<<<spmmH0, TB>>>(bufB, b2, bufC, R0, R1);
    cudaStreamWaitEvent(s2, eC, 0);
    k_spmm<<<spmmH1, TB, 0, s2>>>(bufB, b2, bufC, R1, R2);

    // --- fused final GEMM + maxpool (halves, same-lane deps only) ---
    k_gemm_maxpool<<<gmpH0, 256>>>(bufC, Wl, bl, out, R0, R1);
    k_gemm_maxpool<<<gmpH1, 256, 0, s2>>>(bufC, Wl, bl, out, R1, R2);
    cudaEventRecord(evEnd2, s2);

    // join: harness syncs the default stream
    cudaStreamWaitEvent(0, evEnd2, 0);
}